// round 12
// baseline (speedup 1.0000x reference)
#include <cuda_runtime.h>

// QConv2d: x (B,1,64,64) f32, weights (4,4,3) f32 -> out (B,12,31,31) f32
//
// Closed-form reduction (verified on HW; rel_err 1.8e-7 @ R6/R7):
//   per 4x4 patch: n2 = sum p^2; zn = sum_kh (+,-,+,-)_kh sum_kw (+,-,-,+)_kw p^2;
//   cn = sum_kw p[0]p[3] + p[1]p[2];  x0 = 2cn/n2, z0 = zn/n2;
//   out[c] = cA[c]*x0 + cB[c]*z0 (only qubit-0 U3 survives the trace).
//
// Lane w owns image columns (2w, 2w+1). Per-lane invariants:
//   sq = sum of 8 squares
//   zo = (qa0-qa1+qa2-qa3) - (qb0-qb1+qb2-qb3)   [row signs x col signs +,-]
//   cc = v0*v3 + v1*v2 over both columns
// Patch wo=w: n2 = sq+sq', zn = zo-zo', cn = cc+cc'  (3x shfl.down by 1).
// 2 CTAs per image (load balance), direct coalesced STG.32 stores.

#define IMG_W 64
#define IMG_PIX 4096
#define WO 31
#define LPATCH 961
#define NCH 12
#define OUT_PER_IMG (NCH * LPATCH)           // 11532

__global__ __launch_bounds__(256, 4)
void qconv2d_kernel(const float* __restrict__ x,
                    const float* __restrict__ wts,
                    float* __restrict__ out)
{
    __shared__ float img[34 * IMG_W];        // 8.5 KB slab (16 output rows + halo)
    __shared__ float sA[NCH];
    __shared__ float sB[NCH];

    const int bx   = blockIdx.x;
    const int b    = bx >> 1;
    const int half = bx & 1;
    const int tid  = threadIdx.x;
    const int r0   = half * 32;              // first input row of slab

    // ---- stage input slab (float4, coalesced): 34 rows lower / 32 upper ----
    {
        const int nvec = (half ? 32 : 34) * (IMG_W / 4);
        const float4* src = reinterpret_cast<const float4*>(x)
                          + (size_t)b * (IMG_PIX / 4) + r0 * (IMG_W / 4);
        float4* dst = reinterpret_cast<float4*>(img);
        for (int i = tid; i < nvec; i += 256) dst[i] = src[i];
    }

    // ---- Bloch-rotation coefficients (lanes 0..3 of warp 0) ----
    if (tid < 4) {
        const float th = wts[tid * 12 + 0];
        const float ph = wts[tid * 12 + 1];
        const float om = wts[tid * 12 + 2];
        float st, ct;   sincosf(0.5f * th, &st, &ct);
        const float ct2 = ct * ct, st2 = st * st;
        const float sinth = 2.0f * ct * st;
        const float costh = ct2 - st2;
        float spo, cpo; sincosf(ph + om, &spo, &cpo);
        float smo, cmo; sincosf(ph - om, &smo, &cmo);
        float sp,  cp;  sincosf(ph, &sp, &cp);
        float so,  co;  sincosf(om, &so, &co);
        sA[3 * tid + 0] = ct2 * cpo - st2 * cmo;   // ex <- x0
        sB[3 * tid + 0] = sinth * cp;              // ex <- z0
        sA[3 * tid + 1] = ct2 * spo - st2 * smo;   // ey <- x0
        sB[3 * tid + 1] = sinth * sp;              // ey <- z0
        sA[3 * tid + 2] = -sinth * co;             // ez <- x0
        sB[3 * tid + 2] = costh;                   // ez <- z0
    }
    __syncthreads();

    const int lane = tid & 31;
    const int wrp  = tid >> 5;
    float* ob = out + (size_t)b * OUT_PER_IMG;

    #pragma unroll
    for (int it = 0; it < 2; ++it) {
        const int ho = half * 16 + wrp + it * 8;   // warp-uniform output row
        if (ho <= 30) {
            // lane w owns image columns 2w, 2w+1 of rows 2ho..2ho+3
            const float* rp = img + (2 * ho - r0) * IMG_W + 2 * lane;
            const float2 v0 = *reinterpret_cast<const float2*>(rp);
            const float2 v1 = *reinterpret_cast<const float2*>(rp + IMG_W);
            const float2 v2 = *reinterpret_cast<const float2*>(rp + 2 * IMG_W);
            const float2 v3 = *reinterpret_cast<const float2*>(rp + 3 * IMG_W);

            const float qa0 = v0.x * v0.x, qb0 = v0.y * v0.y;
            const float qa1 = v1.x * v1.x, qb1 = v1.y * v1.y;
            const float qa2 = v2.x * v2.x, qb2 = v2.y * v2.y;
            const float qa3 = v3.x * v3.x, qb3 = v3.y * v3.y;

            const float sq = (qa0 + qb0) + (qa1 + qb1) + (qa2 + qb2) + (qa3 + qb3);
            // row signs (+,-,+,-); own column pair has col signs (+,-)
            const float zo = (qa0 - qa1 + qa2 - qa3) - (qb0 - qb1 + qb2 - qb3);
            const float cc = v0.x * v3.x + v1.x * v2.x + v0.y * v3.y + v1.y * v2.y;

            const float sqn = __shfl_down_sync(0xffffffffu, sq, 1);
            const float zon = __shfl_down_sync(0xffffffffu, zo, 1);
            const float ccn = __shfl_down_sync(0xffffffffu, cc, 1);

            if (lane < WO) {                       // lanes 0..30 output
                const float n2 = sq + sqn;
                const float zn = zo - zon;         // neighbor serves kw=2,3: signs (-,+)
                const float cn = cc + ccn;
                const float inv = __fdividef(1.0f, n2);
                const float x0 = 2.0f * cn * inv;
                const float z0 = zn * inv;
                const int p = ho * WO + lane;      // consecutive across lanes
                #pragma unroll
                for (int c = 0; c < NCH; ++c)
                    ob[c * LPATCH + p] = sA[c] * x0 + sB[c] * z0;
            }
        }
    }
}

extern "C" void kernel_launch(void* const* d_in, const int* in_sizes, int n_in,
                              void* d_out, int out_size)
{
    const float* x   = (const float*)d_in[0];   // (B,1,64,64)
    const float* wts = (const float*)d_in[1];   // (4,4,3)
    float* out = (float*)d_out;                  // (B,12,31,31)
    const int B = in_sizes[0] / IMG_PIX;
    (void)n_in; (void)out_size;
    qconv2d_kernel<<<2 * B, 256>>>(x, wts, out);
}